// round 15
// baseline (speedup 1.0000x reference)
#include <cuda_runtime.h>
#include <cuda_fp16.h>
#include <stdint.h>

#define M_ROWS 16384
#define N_CODES 8192
#define KDIM 256
#define Q_ELEMS (M_ROWS * KDIM)

#define N_TILES 2048            // (16384/256) * (8192/256)
#define N_CLUSTERS 74
#define THREADS 288             // warps 0-7 epilogue, warp 8 producer
#define STAGES 6
#define STAGE_BYTES 32768       // A 16KB + B 16KB per chunk per CTA
#define TC_EN_OFF 1024
#define TC_STAGE0 4096
#define TC_TOTAL (TC_STAGE0 + STAGES * STAGE_BYTES)  // 200704

// mbar smem offsets
#define MB_LOAD 64     // 6 x 8B
#define MB_MMA 112     // 6 x 8B
#define MB_RDY 160     // 6 x 8B (leader-side, follower arrives)
#define MB_DONE 208    // 2 x 8B (per D buffer)
#define MB_EPI 224     // 2 x 8B (leader-side, 2 arrivals each)

#define GATHER_BLOCKS (M_ROWS / 4)   // 4096

// ---------------- persistent scratch ----------------
__device__ unsigned long long g_best[M_ROWS];
__device__ float g_partial[M_ROWS];
__device__ float g_enorm[N_CODES];
__device__ float g_znorm[M_ROWS];
__device__ unsigned int g_ticket;   // zero-initialized; last gather block resets it
// packed, pre-swizzled 128-row blocks: [(tile128*8 + chunk)] -> 16KB contiguous
__device__ __align__(1024) uint4 g_za[(M_ROWS / 128) * 8 * 128 * 8];   // 16 MB
__device__ __align__(1024) uint4 g_zb[(N_CODES / 128) * 8 * 128 * 8];  // 8 MB

// ---------------- common helpers ----------------
__device__ __forceinline__ uint32_t smem_u32(const void* p) {
    uint32_t a;
    asm("{ .reg .u64 t; cvta.to.shared.u64 t, %1; cvt.u32.u64 %0, t; }"
        : "=r"(a) : "l"(p));
    return a;
}
__device__ __forceinline__ unsigned fkey(float f) {
    unsigned u = __float_as_uint(f);
    return (u & 0x80000000u) ? ~u : (u | 0x80000000u);
}
__device__ __forceinline__ float unfkey(unsigned k) {
    unsigned u = (k & 0x80000000u) ? (k & 0x7FFFFFFFu) : ~k;
    return __uint_as_float(u);
}
__device__ __forceinline__ uint32_t h2u(__half a, __half b) {
    __half2 p = __halves2half2(a, b);
    return *reinterpret_cast<uint32_t*>(&p);
}

// ---------------- tcgen05 / TMA helpers (sm_103a cubin pass only) ----------------
#if defined(__CUDA_ARCH_FEAT_SM103_ALL)

__device__ __forceinline__ uint32_t cluster_rank() {
    uint32_t r;
    asm("mov.u32 %0, %%cluster_ctarank;" : "=r"(r));
    return r;
}

#define MBARRIER_INIT(addr, cnt) \
    asm volatile("mbarrier.init.shared.b64 [%0], %1;" :: "r"(addr), "r"(cnt) : "memory")

#define MBARRIER_EXPECT_TX(mbar, bytes) \
    asm volatile("mbarrier.arrive.expect_tx.shared.b64 _, [%0], %1;" \
                 :: "r"(mbar), "r"(bytes) : "memory")

#define MBARRIER_ARRIVE(mbar) \
    asm volatile("mbarrier.arrive.shared.b64 _, [%0];" :: "r"(mbar) : "memory")

// arrive on the same-offset mbarrier in cluster CTA 0 (leader)
#define MBARRIER_ARRIVE_LEADER(mbar) \
    asm volatile( \
        "{\n\t.reg .b32 remAddr;\n\t" \
        "mapa.shared::cluster.u32 remAddr, %0, 0;\n\t" \
        "mbarrier.arrive.shared::cluster.b64 _, [remAddr];\n\t}" \
        :: "r"(mbar) : "memory")

#define CP_BULK(dst, src, bytes, mbar) \
    asm volatile("cp.async.bulk.shared::cluster.global.mbarrier::complete_tx::bytes " \
                 "[%0], [%1], %2, [%3];" \
                 :: "r"(dst), "l"(src), "r"(bytes), "r"(mbar) : "memory")

#define MBARRIER_WAIT_PARITY(mbar, parity) do {                                   \
    uint32_t _m = (mbar); uint32_t _p = (parity); uint32_t _done;                 \
    asm volatile("{\n\t.reg .pred p;\n\t"                                         \
        "mbarrier.try_wait.parity.acquire.cta.shared::cta.b64 p, [%1], %2;\n\t"   \
        "selp.b32 %0, 1, 0, p;\n\t}" : "=r"(_done) : "r"(_m), "r"(_p) : "memory");\
    if (!_done) {                                                                 \
        asm volatile("{\n\t.reg .pred P1;\n\t"                                    \
            "WAIT_LOOP_%=:\n\t"                                                   \
            "mbarrier.try_wait.parity.acquire.cta.shared::cta.b64 P1, [%0], %1, 0x989680;\n\t" \
            "@P1 bra.uni WAIT_DONE_%=;\n\t"                                       \
            "bra.uni WAIT_LOOP_%=;\n\t"                                           \
            "WAIT_DONE_%=:\n\t}" :: "r"(_m), "r"(_p) : "memory");                 \
    }                                                                             \
} while (0)

// cluster-scope acquire variant (pairs with cross-CTA release-arrive)
#define MBARRIER_WAIT_PARITY_CL(mbar, parity) do {                                \
    uint32_t _m = (mbar); uint32_t _p = (parity); uint32_t _done;                 \
    asm volatile("{\n\t.reg .pred p;\n\t"                                         \
        "mbarrier.try_wait.parity.acquire.cluster.shared::cta.b64 p, [%1], %2;\n\t" \
        "selp.b32 %0, 1, 0, p;\n\t}" : "=r"(_done) : "r"(_m), "r"(_p) : "memory");\
    if (!_done) {                                                                 \
        asm volatile("{\n\t.reg .pred P1;\n\t"                                    \
            "WAIT_LOOP_%=:\n\t"                                                   \
            "mbarrier.try_wait.parity.acquire.cluster.shared::cta.b64 P1, [%0], %1, 0x989680;\n\t" \
            "@P1 bra.uni WAIT_DONE_%=;\n\t"                                       \
            "bra.uni WAIT_LOOP_%=;\n\t"                                           \
            "WAIT_DONE_%=:\n\t}" :: "r"(_m), "r"(_p) : "memory");                 \
    }                                                                             \
} while (0)

#define TCGEN05_ALLOC_CG2(smem_dst, ncols) \
    asm volatile("tcgen05.alloc.cta_group::2.sync.aligned.shared::cta.b32 [%0], %1;" \
                 :: "r"(smem_dst), "r"(ncols) : "memory")
#define TCGEN05_DEALLOC_CG2(tmem, ncols) \
    asm volatile("tcgen05.dealloc.cta_group::2.sync.aligned.b32 %0, %1;" :: "r"(tmem), "r"(ncols))
#define TCGEN05_RELINQUISH_CG2() \
    asm volatile("tcgen05.relinquish_alloc_permit.cta_group::2.sync.aligned;")
#define TCGEN05_COMMIT_MC(mbar) \
    asm volatile("tcgen05.commit.cta_group::2.mbarrier::arrive::one.shared::cluster.multicast::cluster.b64 [%0], %1;" \
                 :: "r"(mbar), "h"((uint16_t)3) : "memory")
#define TCGEN05_FENCE_AFTER() asm volatile("tcgen05.fence::after_thread_sync;" ::: "memory")
#define TCGEN05_FENCE_BEFORE() asm volatile("tcgen05.fence::before_thread_sync;" ::: "memory")
#define TCGEN05_WAIT_LD() asm volatile("tcgen05.wait::ld.sync.aligned;" ::: "memory")

#define CLUSTER_SYNC() do { \
    asm volatile("barrier.cluster.arrive.aligned;" ::: "memory"); \
    asm volatile("barrier.cluster.wait.aligned;" ::: "memory"); \
} while (0)

#define TCGEN05_LD_32X32B_X32(r, tmem_addr) \
    asm volatile( \
        "tcgen05.ld.sync.aligned.32x32b.x32.b32 " \
        "{%0, %1, %2, %3, %4, %5, %6, %7, " \
        " %8, %9, %10, %11, %12, %13, %14, %15, " \
        " %16, %17, %18, %19, %20, %21, %22, %23, " \
        " %24, %25, %26, %27, %28, %29, %30, %31}, [%32];" \
        : "=r"((r)[0]),  "=r"((r)[1]),  "=r"((r)[2]),  "=r"((r)[3]), \
          "=r"((r)[4]),  "=r"((r)[5]),  "=r"((r)[6]),  "=r"((r)[7]), \
          "=r"((r)[8]),  "=r"((r)[9]),  "=r"((r)[10]), "=r"((r)[11]), \
          "=r"((r)[12]), "=r"((r)[13]), "=r"((r)[14]), "=r"((r)[15]), \
          "=r"((r)[16]), "=r"((r)[17]), "=r"((r)[18]), "=r"((r)[19]), \
          "=r"((r)[20]), "=r"((r)[21]), "=r"((r)[22]), "=r"((r)[23]), \
          "=r"((r)[24]), "=r"((r)[25]), "=r"((r)[26]), "=r"((r)[27]), \
          "=r"((r)[28]), "=r"((r)[29]), "=r"((r)[30]), "=r"((r)[31]) \
        : "r"(tmem_addr))

// SW128 descriptor: version=1, LBO=1, SBO=64 (128B rows, 8x128B atom)
static __device__ __forceinline__ unsigned long long make_desc(uint32_t addr) {
    const unsigned long long base =
        (2ull << 61) | (1ull << 46) | (64ull << 32) | (1ull << 16);
    return base | ((unsigned long long)(addr >> 4) & 0x3FFFull);
}

// idesc kind::f16 cg2: D=F32(1@4), A=FP16(0), B=FP16(0), N=256 (32@17), M=256 (16@24)
#define TC_IDESC ((1u << 4) | (32u << 17) | (16u << 24))

__device__ __forceinline__ void mma_f16_ss_cg2(uint32_t d, unsigned long long ad,
                                               unsigned long long bd, uint32_t en) {
    asm volatile(
        "{\n\t.reg .pred p;\n\t"
        "setp.ne.u32 p, %5, 0;\n\t"
        "tcgen05.mma.cta_group::2.kind::f16 [%0], %1, %2, %3, "
        "{%4, %4, %4, %4, %4, %4, %4, %4}, p;\n\t}"
        :: "r"(d), "l"(ad), "l"(bd), "r"((uint32_t)TC_IDESC), "r"(0u), "r"(en)
        : "memory");
}

#endif  // __CUDA_ARCH_FEAT_SM103_ALL

// ---------------- fused prep: split + pack + pre-swizzle + norms ----------------
// 128-row blocks; row r, 16B unit u: u=c^(r&7) -> hi halves; u=(c+4)^(r&7) -> lo.
// Grid: first 2048 blocks pack z (and znorm, g_best init); next 1024 pack e (+enorm).
__global__ void pack_kernel(const float* __restrict__ z, const float* __restrict__ emb) {
    const int isz = (blockIdx.x < 2048) ? 1 : 0;
    int gid = (isz ? blockIdx.x : (blockIdx.x - 2048)) * 256 + threadIdx.x;
    int c = gid & 3, s = (gid >> 2) & 7, grow = gid >> 5;
    const float* src = isz ? z : emb;
    const float4* p4 = (const float4*)(src + (size_t)grow * KDIM + s * 32 + c * 8);
    float4 a = p4[0], b = p4[1];
    __half h0 = __float2half(a.x), h1 = __float2half(a.y);
    __half h2 = __float2half(a.z), h3 = __float2half(a.w);
    __half h4 = __float2half(b.x), h5 = __float2half(b.y);
    __half h6 = __float2half(b.z), h7 = __float2half(b.w);
    uint4 hv, lv;
    hv.x = h2u(h0, h1); hv.y = h2u(h2, h3); hv.z = h2u(h4, h5); hv.w = h2u(h6, h7);
    lv.x = h2u(__float2half(a.x - __half2float(h0)), __float2half(a.y - __half2float(h1)));
    lv.y = h2u(__float2half(a.z - __half2float(h2)), __float2half(a.w - __half2float(h3)));
    lv.z = h2u(__float2half(b.x - __half2float(h4)), __float2half(b.y - __half2float(h5)));
    lv.w = h2u(__float2half(b.z - __half2float(h6)), __float2half(b.w - __half2float(h7)));
    int blk = grow >> 7, r = grow & 127;
    size_t rowbase = ((size_t)(blk * 8 + s) * 128 + r) * 8;
    uint4* dst = isz ? g_za : g_zb;
    dst[rowbase + (c ^ (r & 7))] = hv;
    dst[rowbase + ((c + 4) ^ (r & 7))] = lv;

    // per-row squared norm (32 consecutive threads = one row)
    float nrm = a.x * a.x;
    nrm = fmaf(a.y, a.y, nrm); nrm = fmaf(a.z, a.z, nrm); nrm = fmaf(a.w, a.w, nrm);
    nrm = fmaf(b.x, b.x, nrm); nrm = fmaf(b.y, b.y, nrm);
    nrm = fmaf(b.z, b.z, nrm); nrm = fmaf(b.w, b.w, nrm);
#pragma unroll
    for (int o = 16; o; o >>= 1) nrm += __shfl_xor_sync(0xffffffffu, nrm, o);
    if ((gid & 31) == 0) {
        if (isz) g_znorm[grow] = nrm;
        else g_enorm[grow] = nrm;
    }
    if (isz && gid < M_ROWS) g_best[gid] = ~0ull;
}

// ---------------- persistent 2CTA GEMM + argmin ----------------
__global__ void __launch_bounds__(THREADS, 1) __cluster_dims__(2, 1, 1)
vq_gemm_kernel() {
    extern __shared__ __align__(1024) char smem[];
    const int tid = threadIdx.x;

#if defined(__CUDA_ARCH_FEAT_SM103_ALL)
    const uint32_t sb = smem_u32(smem);
    const uint32_t rank = cluster_rank();
    const int cid = blockIdx.x >> 1;

    if ((tid >> 5) == 8) {
        TCGEN05_ALLOC_CG2(sb, 512);
        TCGEN05_RELINQUISH_CG2();
    }
    if (tid == 0) {
#pragma unroll
        for (int i = 0; i < STAGES; i++) {
            MBARRIER_INIT(sb + MB_LOAD + i * 8, 1);
            MBARRIER_INIT(sb + MB_MMA + i * 8, 1);
            MBARRIER_INIT(sb + MB_RDY + i * 8, 1);
        }
        MBARRIER_INIT(sb + MB_DONE + 0, 1);
        MBARRIER_INIT(sb + MB_DONE + 8, 1);
        MBARRIER_INIT(sb + MB_EPI + 0, 2);
        MBARRIER_INIT(sb + MB_EPI + 8, 2);
    }
    __syncthreads();
    CLUSTER_SYNC();   // mbars + TMEM alloc visible cluster-wide

    uint32_t tmem_base;
    asm volatile("ld.shared.b32 %0, [%1];" : "=r"(tmem_base) : "r"(sb));

    if (tid >= 256) {
        // ================== PRODUCER (warp 8; only tid 256 acts) ==================
        if (tid == 256) {
            auto issue_load = [&](int lc2) {
                int t2 = cid + N_CLUSTERS * (lc2 >> 3);
                if (t2 >= N_TILES) return;
                int s2 = lc2 & 7, b2 = lc2 % STAGES;
                uint32_t dst = sb + TC_STAGE0 + (uint32_t)b2 * STAGE_BYTES;
                int mblk = ((t2 >> 5) * 2 + (int)rank) * 8 + s2;
                int nblk = ((t2 & 31) * 2 + (int)rank) * 8 + s2;
                uint32_t mb = sb + MB_LOAD + b2 * 8;
                MBARRIER_EXPECT_TX(mb, 32768u);
                CP_BULK(dst, (const char*)g_za + (size_t)mblk * 16384u, 16384u, mb);
                CP_BULK(dst + 16384u, (const char*)g_zb + (size_t)nblk * 16384u, 16384u, mb);
            };

#pragma unroll
            for (int i = 0; i < STAGES - 1; i++) issue_load(i);
            int lc = 0, tc = 0;
            for (int t = cid; t < N_TILES; t += N_CLUSTERS, tc++) {
                for (int s = 0; s < 8; s++, lc++) {
                    const int buf = lc % STAGES;
                    const uint32_t ph = (uint32_t)((lc / STAGES) & 1);
                    MBARRIER_WAIT_PARITY(sb + MB_LOAD + buf * 8, ph);

                    if (rank == 0) {
                        MBARRIER_WAIT_PARITY_CL(sb + MB_RDY + buf * 8, ph);
                        if (s == 0 && tc >= 2) {
                            MBARRIER_WAIT_PARITY_CL(sb + MB_EPI + (tc & 1) * 8,
                                                    (uint32_t)(((tc - 2) >> 1) & 1));
                            TCGEN05_FENCE_AFTER();
                        }
                        uint32_t abase = sb + TC_STAGE0 + (uint32_t)buf * STAGE_BYTES;
                        unsigned long long ad = make_desc(abase);
                        unsigned long long bd = make_desc(abase + 16384u);
                        uint32_t dcol = tmem_base + (uint32_t)((tc & 1) * 256);
#pragma unroll
                        for (int p = 0; p < 3; p++) {
                            const int ao = (p == 2) ? 4 : 0;
                            const int bo = (p == 1) ? 4 : 0;
#pragma unroll
                            for (int ks = 0; ks < 2; ks++) {
                                uint32_t en = (s == 0 && p == 0 && ks == 0) ? 0u : 1u;
                                mma_f16_ss_cg2(dcol, ad + ao + ks * 2, bd + bo + ks * 2, en);
                            }
                        }
                        TCGEN05_COMMIT_MC(sb + MB_MMA + buf * 8);
                        if (s == 7) TCGEN05_COMMIT_MC(sb + MB_DONE + (tc & 1) * 8);
                    } else {
                        MBARRIER_ARRIVE_LEADER(sb + MB_RDY + buf * 8);
                    }

                    // buffer (lc+STAGES-1)%STAGES was last used by chunk lc-1
                    if (lc >= 1)
                        MBARRIER_WAIT_PARITY(sb + MB_MMA + ((lc - 1) % STAGES) * 8,
                                             (uint32_t)(((lc - 1) / STAGES) & 1));
                    issue_load(lc + STAGES - 1);
                }
            }
        }
    } else {
        // ================== EPILOGUE (warps 0-7, each CTA reads its own D) ==================
        const int w = tid >> 5;
        const int lane = tid & 31;
        const int sub = w & 3;
        const int grp = w >> 2;   // col half within N=256
        float* en = (float*)(smem + TC_EN_OFF);
        int tc = 0;
        for (int t = cid; t < N_TILES; t += N_CLUSTERS, tc++) {
            const int nt = t & 31;
            const int mt = t >> 5;
            en[tid] = g_enorm[nt * 256 + tid];
            asm volatile("bar.sync 1, 256;" ::: "memory");

            MBARRIER_WAIT_PARITY(sb + MB_DONE + (tc & 1) * 8, (uint32_t)((tc >> 1) & 1));
            TCGEN05_FENCE_AFTER();

            const uint32_t dbase = tmem_base + (uint32_t)((tc & 1) * 256) + grp * 128;
            float dmin = 3.4e38f;
            int besti = 0;
#pragma unroll
            for (int c0 = 0; c0 < 128; c0 += 32) {
                uint32_t r[32];
                TCGEN05_LD_32X32B_X32(r, dbase + c0);
                TCGEN05_WAIT_LD();
#pragma unroll
                for (int j = 0; j < 32; j++) {
                    int nl = grp * 128 + c0 + j;
                    float d = en[nl] - 2.0f * __uint_as_float(r[j]);
                    if (d < dmin) { dmin = d; besti = nl; }
                }
            }
            TCGEN05_FENCE_BEFORE();
            asm volatile("bar.sync 1, 256;" ::: "memory");  // all D + en reads done
            if (tid == 0) {
                if (rank == 0) MBARRIER_ARRIVE(sb + MB_EPI + (tc & 1) * 8);
                else MBARRIER_ARRIVE_LEADER(sb + MB_EPI + (tc & 1) * 8);
            }

            const int mrow = mt * 256 + (int)rank * 128 + sub * 32 + lane;
            unsigned long long key =
                ((unsigned long long)fkey(dmin) << 32) | (unsigned)(nt * 256 + besti);
            atomicMin(&g_best[mrow], key);
        }
    }

    __syncthreads();
    if ((tid >> 5) == 8) TCGEN05_DEALLOC_CG2(tmem_base, 512);
    CLUSTER_SYNC();

#else
    // PTX-pass body: compile-only; the sm_103a cubin above is what executes.
    (void)tid;
#endif
}

// ---------------- gather + loss (finalize fused via last-block reduction) ----------------
// loss per row recovered from the argmin key: ||q-z||^2 = dmin + ||z||^2
__global__ void gather_kernel(const float* __restrict__ emb,
                              float* __restrict__ out, int has_extra) {
    __shared__ bool s_last;
    __shared__ float sh[256];
    const int tid = threadIdx.x;
    const int r = tid >> 6;
    const int c = tid & 63;
    const int row = blockIdx.x * 4 + r;
    unsigned long long key = g_best[row];
    int idx = (int)(key & 0xFFFFFFFFull);

    ((float4*)out)[(size_t)row * 64 + c] = ((const float4*)emb)[(size_t)idx * 64 + c];

    if (c == 0) {
        g_partial[row] = unfkey((unsigned)(key >> 32)) + g_znorm[row];
        if (has_extra) out[Q_ELEMS + 1 + row] = (float)idx;
    }

    // last block performs the (deterministic, fixed-order) loss reduction
    __threadfence();
    if (tid == 0) {
        unsigned tkt = atomicAdd(&g_ticket, 1u);
        s_last = (tkt == GATHER_BLOCKS - 1);
        if (s_last) g_ticket = 0;   // reset for next graph replay
    }
    __syncthreads();
    if (!s_last || !has_extra) return;

    float s = 0.f;
    const float4* p4 = (const float4*)g_partial;
#pragma unroll
    for (int i = 0; i < 16; i++) {
        float4 v = p4[tid + i * 256];
        s += (v.x + v.y) + (v.z + v.w);
    }
    sh[tid] = s;
    __syncthreads();
#pragma unroll
    for (int o = 128; o >= 32; o >>= 1) {
        if (tid < o) sh[tid] += sh[tid + o];
        __syncthreads();
    }
    if (tid < 32) {
        float v = sh[tid];
#pragma unroll
        for (int o = 16; o; o >>= 1) v += __shfl_xor_sync(0xffffffffu, v, o);
        if (tid == 0) out[Q_ELEMS] = 1.25f * v / (float)Q_ELEMS;
    }
}

// ---------------- launcher ----------------
extern "C" void kernel_launch(void* const* d_in, const int* in_sizes, int n_in,
                              void* d_out, int out_size) {
    const float* z;
    const float* emb;
    if (in_sizes[0] == M_ROWS * KDIM) {
        z = (const float*)d_in[0];
        emb = (const float*)d_in[1];
    } else {
        z = (const float*)d_in[1];
        emb = (const float*)d_in[0];
    }
    float* out = (float*)d_out;
    int has_extra = (out_size >= Q_ELEMS + 1 + M_ROWS) ? 1 : 0;

    cudaFuncSetAttribute(vq_gemm_kernel,
                         cudaFuncAttributeMaxDynamicSharedMemorySize, TC_TOTAL);

    pack_kernel<<<3072, 256>>>(z, emb);   // z blocks [0,2048), e blocks [2048,3072)

    vq_gemm_kernel<<<2 * N_CLUSTERS, THREADS, TC_TOTAL>>>();

    gather_kernel<<<GATHER_BLOCKS, 256>>>(emb, out, has_extra);
}

// round 16
// speedup vs baseline: 1.0397x; 1.0397x over previous
#include <cuda_runtime.h>
#include <cuda_fp16.h>
#include <stdint.h>

#define M_ROWS 16384
#define N_CODES 8192
#define KDIM 256
#define Q_ELEMS (M_ROWS * KDIM)

#define N_TILES 2048            // (16384/256) * (8192/256)
#define N_CLUSTERS 74
#define THREADS 288             // warps 0-7 epilogue, warp 8 producer
#define STAGES 6
#define STAGE_BYTES 32768       // A 16KB + B 16KB per chunk per CTA
#define TC_EN_OFF 1024
#define TC_STAGE0 4096
#define TC_TOTAL (TC_STAGE0 + STAGES * STAGE_BYTES)  // 200704

// mbar smem offsets
#define MB_LOAD 64     // 6 x 8B
#define MB_MMA 112     // 6 x 8B
#define MB_RDY 160     // 6 x 8B (leader-side, follower arrives)
#define MB_DONE 208    // 2 x 8B (per D buffer)
#define MB_EPI 224     // 2 x 8B (leader-side, 2 arrivals each)

// ---------------- persistent scratch ----------------
__device__ unsigned long long g_best[M_ROWS];
__device__ float g_partial[M_ROWS];
__device__ float g_enorm[N_CODES];
__device__ float g_znorm[M_ROWS];
// packed, pre-swizzled 128-row blocks: [(tile128*8 + chunk)] -> 16KB contiguous
__device__ __align__(1024) uint4 g_za[(M_ROWS / 128) * 8 * 128 * 8];   // 16 MB
__device__ __align__(1024) uint4 g_zb[(N_CODES / 128) * 8 * 128 * 8];  // 8 MB

// ---------------- common helpers ----------------
__device__ __forceinline__ uint32_t smem_u32(const void* p) {
    uint32_t a;
    asm("{ .reg .u64 t; cvta.to.shared.u64 t, %1; cvt.u32.u64 %0, t; }"
        : "=r"(a) : "l"(p));
    return a;
}
__device__ __forceinline__ unsigned fkey(float f) {
    unsigned u = __float_as_uint(f);
    return (u & 0x80000000u) ? ~u : (u | 0x80000000u);
}
__device__ __forceinline__ float unfkey(unsigned k) {
    unsigned u = (k & 0x80000000u) ? (k & 0x7FFFFFFFu) : ~k;
    return __uint_as_float(u);
}
__device__ __forceinline__ uint32_t h2u(__half a, __half b) {
    __half2 p = __halves2half2(a, b);
    return *reinterpret_cast<uint32_t*>(&p);
}

// ---------------- tcgen05 / TMA helpers (sm_103a cubin pass only) ----------------
#if defined(__CUDA_ARCH_FEAT_SM103_ALL)

__device__ __forceinline__ uint32_t cluster_rank() {
    uint32_t r;
    asm("mov.u32 %0, %%cluster_ctarank;" : "=r"(r));
    return r;
}

#define MBARRIER_INIT(addr, cnt) \
    asm volatile("mbarrier.init.shared.b64 [%0], %1;" :: "r"(addr), "r"(cnt) : "memory")

#define MBARRIER_EXPECT_TX(mbar, bytes) \
    asm volatile("mbarrier.arrive.expect_tx.shared.b64 _, [%0], %1;" \
                 :: "r"(mbar), "r"(bytes) : "memory")

#define MBARRIER_ARRIVE(mbar) \
    asm volatile("mbarrier.arrive.shared.b64 _, [%0];" :: "r"(mbar) : "memory")

// arrive on the same-offset mbarrier in cluster CTA 0 (leader)
#define MBARRIER_ARRIVE_LEADER(mbar) \
    asm volatile( \
        "{\n\t.reg .b32 remAddr;\n\t" \
        "mapa.shared::cluster.u32 remAddr, %0, 0;\n\t" \
        "mbarrier.arrive.shared::cluster.b64 _, [remAddr];\n\t}" \
        :: "r"(mbar) : "memory")

#define CP_BULK(dst, src, bytes, mbar) \
    asm volatile("cp.async.bulk.shared::cluster.global.mbarrier::complete_tx::bytes " \
                 "[%0], [%1], %2, [%3];" \
                 :: "r"(dst), "l"(src), "r"(bytes), "r"(mbar) : "memory")

#define MBARRIER_WAIT_PARITY(mbar, parity) do {                                   \
    uint32_t _m = (mbar); uint32_t _p = (parity); uint32_t _done;                 \
    asm volatile("{\n\t.reg .pred p;\n\t"                                         \
        "mbarrier.try_wait.parity.acquire.cta.shared::cta.b64 p, [%1], %2;\n\t"   \
        "selp.b32 %0, 1, 0, p;\n\t}" : "=r"(_done) : "r"(_m), "r"(_p) : "memory");\
    if (!_done) {                                                                 \
        asm volatile("{\n\t.reg .pred P1;\n\t"                                    \
            "WAIT_LOOP_%=:\n\t"                                                   \
            "mbarrier.try_wait.parity.acquire.cta.shared::cta.b64 P1, [%0], %1, 0x989680;\n\t" \
            "@P1 bra.uni WAIT_DONE_%=;\n\t"                                       \
            "bra.uni WAIT_LOOP_%=;\n\t"                                           \
            "WAIT_DONE_%=:\n\t}" :: "r"(_m), "r"(_p) : "memory");                 \
    }                                                                             \
} while (0)

// cluster-scope acquire variant (pairs with cross-CTA release-arrive)
#define MBARRIER_WAIT_PARITY_CL(mbar, parity) do {                                \
    uint32_t _m = (mbar); uint32_t _p = (parity); uint32_t _done;                 \
    asm volatile("{\n\t.reg .pred p;\n\t"                                         \
        "mbarrier.try_wait.parity.acquire.cluster.shared::cta.b64 p, [%1], %2;\n\t" \
        "selp.b32 %0, 1, 0, p;\n\t}" : "=r"(_done) : "r"(_m), "r"(_p) : "memory");\
    if (!_done) {                                                                 \
        asm volatile("{\n\t.reg .pred P1;\n\t"                                    \
            "WAIT_LOOP_%=:\n\t"                                                   \
            "mbarrier.try_wait.parity.acquire.cluster.shared::cta.b64 P1, [%0], %1, 0x989680;\n\t" \
            "@P1 bra.uni WAIT_DONE_%=;\n\t"                                       \
            "bra.uni WAIT_LOOP_%=;\n\t"                                           \
            "WAIT_DONE_%=:\n\t}" :: "r"(_m), "r"(_p) : "memory");                 \
    }                                                                             \
} while (0)

#define TCGEN05_ALLOC_CG2(smem_dst, ncols) \
    asm volatile("tcgen05.alloc.cta_group::2.sync.aligned.shared::cta.b32 [%0], %1;" \
                 :: "r"(smem_dst), "r"(ncols) : "memory")
#define TCGEN05_DEALLOC_CG2(tmem, ncols) \
    asm volatile("tcgen05.dealloc.cta_group::2.sync.aligned.b32 %0, %1;" :: "r"(tmem), "r"(ncols))
#define TCGEN05_RELINQUISH_CG2() \
    asm volatile("tcgen05.relinquish_alloc_permit.cta_group::2.sync.aligned;")
#define TCGEN05_COMMIT_MC(mbar) \
    asm volatile("tcgen05.commit.cta_group::2.mbarrier::arrive::one.shared::cluster.multicast::cluster.b64 [%0], %1;" \
                 :: "r"(mbar), "h"((uint16_t)3) : "memory")
#define TCGEN05_FENCE_AFTER() asm volatile("tcgen05.fence::after_thread_sync;" ::: "memory")
#define TCGEN05_FENCE_BEFORE() asm volatile("tcgen05.fence::before_thread_sync;" ::: "memory")
#define TCGEN05_WAIT_LD() asm volatile("tcgen05.wait::ld.sync.aligned;" ::: "memory")

#define CLUSTER_SYNC() do { \
    asm volatile("barrier.cluster.arrive.aligned;" ::: "memory"); \
    asm volatile("barrier.cluster.wait.aligned;" ::: "memory"); \
} while (0)

#define TCGEN05_LD_32X32B_X32(r, tmem_addr) \
    asm volatile( \
        "tcgen05.ld.sync.aligned.32x32b.x32.b32 " \
        "{%0, %1, %2, %3, %4, %5, %6, %7, " \
        " %8, %9, %10, %11, %12, %13, %14, %15, " \
        " %16, %17, %18, %19, %20, %21, %22, %23, " \
        " %24, %25, %26, %27, %28, %29, %30, %31}, [%32];" \
        : "=r"((r)[0]),  "=r"((r)[1]),  "=r"((r)[2]),  "=r"((r)[3]), \
          "=r"((r)[4]),  "=r"((r)[5]),  "=r"((r)[6]),  "=r"((r)[7]), \
          "=r"((r)[8]),  "=r"((r)[9]),  "=r"((r)[10]), "=r"((r)[11]), \
          "=r"((r)[12]), "=r"((r)[13]), "=r"((r)[14]), "=r"((r)[15]), \
          "=r"((r)[16]), "=r"((r)[17]), "=r"((r)[18]), "=r"((r)[19]), \
          "=r"((r)[20]), "=r"((r)[21]), "=r"((r)[22]), "=r"((r)[23]), \
          "=r"((r)[24]), "=r"((r)[25]), "=r"((r)[26]), "=r"((r)[27]), \
          "=r"((r)[28]), "=r"((r)[29]), "=r"((r)[30]), "=r"((r)[31]) \
        : "r"(tmem_addr))

// SW128 descriptor: version=1, LBO=1, SBO=64 (128B rows, 8x128B atom)
static __device__ __forceinline__ unsigned long long make_desc(uint32_t addr) {
    const unsigned long long base =
        (2ull << 61) | (1ull << 46) | (64ull << 32) | (1ull << 16);
    return base | ((unsigned long long)(addr >> 4) & 0x3FFFull);
}

// idesc kind::f16 cg2: D=F32(1@4), A=FP16(0), B=FP16(0), N=256 (32@17), M=256 (16@24)
#define TC_IDESC ((1u << 4) | (32u << 17) | (16u << 24))

__device__ __forceinline__ void mma_f16_ss_cg2(uint32_t d, unsigned long long ad,
                                               unsigned long long bd, uint32_t en) {
    asm volatile(
        "{\n\t.reg .pred p;\n\t"
        "setp.ne.u32 p, %5, 0;\n\t"
        "tcgen05.mma.cta_group::2.kind::f16 [%0], %1, %2, %3, "
        "{%4, %4, %4, %4, %4, %4, %4, %4}, p;\n\t}"
        :: "r"(d), "l"(ad), "l"(bd), "r"((uint32_t)TC_IDESC), "r"(0u), "r"(en)
        : "memory");
}

#endif  // __CUDA_ARCH_FEAT_SM103_ALL

// ---------------- fused prep: split + pack + pre-swizzle + norms ----------------
// 128-row blocks; row r, 16B unit u: u=c^(r&7) -> hi halves; u=(c+4)^(r&7) -> lo.
// Grid: first 2048 blocks pack z (and znorm, g_best init); next 1024 pack e (+enorm).
__global__ void pack_kernel(const float* __restrict__ z, const float* __restrict__ emb) {
    const int isz = (blockIdx.x < 2048) ? 1 : 0;
    int gid = (isz ? blockIdx.x : (blockIdx.x - 2048)) * 256 + threadIdx.x;
    int c = gid & 3, s = (gid >> 2) & 7, grow = gid >> 5;
    const float* src = isz ? z : emb;
    const float4* p4 = (const float4*)(src + (size_t)grow * KDIM + s * 32 + c * 8);
    float4 a = p4[0], b = p4[1];
    __half h0 = __float2half(a.x), h1 = __float2half(a.y);
    __half h2 = __float2half(a.z), h3 = __float2half(a.w);
    __half h4 = __float2half(b.x), h5 = __float2half(b.y);
    __half h6 = __float2half(b.z), h7 = __float2half(b.w);
    uint4 hv, lv;
    hv.x = h2u(h0, h1); hv.y = h2u(h2, h3); hv.z = h2u(h4, h5); hv.w = h2u(h6, h7);
    lv.x = h2u(__float2half(a.x - __half2float(h0)), __float2half(a.y - __half2float(h1)));
    lv.y = h2u(__float2half(a.z - __half2float(h2)), __float2half(a.w - __half2float(h3)));
    lv.z = h2u(__float2half(b.x - __half2float(h4)), __float2half(b.y - __half2float(h5)));
    lv.w = h2u(__float2half(b.z - __half2float(h6)), __float2half(b.w - __half2float(h7)));
    int blk = grow >> 7, r = grow & 127;
    size_t rowbase = ((size_t)(blk * 8 + s) * 128 + r) * 8;
    uint4* dst = isz ? g_za : g_zb;
    dst[rowbase + (c ^ (r & 7))] = hv;
    dst[rowbase + ((c + 4) ^ (r & 7))] = lv;

    // per-row squared norm (32 consecutive threads = one row)
    float nrm = a.x * a.x;
    nrm = fmaf(a.y, a.y, nrm); nrm = fmaf(a.z, a.z, nrm); nrm = fmaf(a.w, a.w, nrm);
    nrm = fmaf(b.x, b.x, nrm); nrm = fmaf(b.y, b.y, nrm);
    nrm = fmaf(b.z, b.z, nrm); nrm = fmaf(b.w, b.w, nrm);
#pragma unroll
    for (int o = 16; o; o >>= 1) nrm += __shfl_xor_sync(0xffffffffu, nrm, o);
    if ((gid & 31) == 0) {
        if (isz) g_znorm[grow] = nrm;
        else g_enorm[grow] = nrm;
    }
    if (isz && gid < M_ROWS) g_best[gid] = ~0ull;
}

// ---------------- persistent 2CTA GEMM + argmin ----------------
__global__ void __launch_bounds__(THREADS, 1) __cluster_dims__(2, 1, 1)
vq_gemm_kernel() {
    extern __shared__ __align__(1024) char smem[];
    const int tid = threadIdx.x;

#if defined(__CUDA_ARCH_FEAT_SM103_ALL)
    const uint32_t sb = smem_u32(smem);
    const uint32_t rank = cluster_rank();
    const int cid = blockIdx.x >> 1;

    if ((tid >> 5) == 8) {
        TCGEN05_ALLOC_CG2(sb, 512);
        TCGEN05_RELINQUISH_CG2();
    }
    if (tid == 0) {
#pragma unroll
        for (int i = 0; i < STAGES; i++) {
            MBARRIER_INIT(sb + MB_LOAD + i * 8, 1);
            MBARRIER_INIT(sb + MB_MMA + i * 8, 1);
            MBARRIER_INIT(sb + MB_RDY + i * 8, 1);
        }
        MBARRIER_INIT(sb + MB_DONE + 0, 1);
        MBARRIER_INIT(sb + MB_DONE + 8, 1);
        MBARRIER_INIT(sb + MB_EPI + 0, 2);
        MBARRIER_INIT(sb + MB_EPI + 8, 2);
    }
    __syncthreads();
    CLUSTER_SYNC();   // mbars + TMEM alloc visible cluster-wide

    uint32_t tmem_base;
    asm volatile("ld.shared.b32 %0, [%1];" : "=r"(tmem_base) : "r"(sb));

    if (tid >= 256) {
        // ================== PRODUCER (warp 8; only tid 256 acts) ==================
        if (tid == 256) {
            auto issue_load = [&](int lc2) {
                int t2 = cid + N_CLUSTERS * (lc2 >> 3);
                if (t2 >= N_TILES) return;
                int s2 = lc2 & 7, b2 = lc2 % STAGES;
                uint32_t dst = sb + TC_STAGE0 + (uint32_t)b2 * STAGE_BYTES;
                int mblk = ((t2 >> 5) * 2 + (int)rank) * 8 + s2;
                int nblk = ((t2 & 31) * 2 + (int)rank) * 8 + s2;
                uint32_t mb = sb + MB_LOAD + b2 * 8;
                MBARRIER_EXPECT_TX(mb, 32768u);
                CP_BULK(dst, (const char*)g_za + (size_t)mblk * 16384u, 16384u, mb);
                CP_BULK(dst + 16384u, (const char*)g_zb + (size_t)nblk * 16384u, 16384u, mb);
            };

#pragma unroll
            for (int i = 0; i < STAGES - 1; i++) issue_load(i);
            int lc = 0, tc = 0;
            for (int t = cid; t < N_TILES; t += N_CLUSTERS, tc++) {
                for (int s = 0; s < 8; s++, lc++) {
                    const int buf = lc % STAGES;
                    const uint32_t ph = (uint32_t)((lc / STAGES) & 1);
                    MBARRIER_WAIT_PARITY(sb + MB_LOAD + buf * 8, ph);

                    if (rank == 0) {
                        MBARRIER_WAIT_PARITY_CL(sb + MB_RDY + buf * 8, ph);
                        if (s == 0 && tc >= 2) {
                            MBARRIER_WAIT_PARITY_CL(sb + MB_EPI + (tc & 1) * 8,
                                                    (uint32_t)(((tc - 2) >> 1) & 1));
                            TCGEN05_FENCE_AFTER();
                        }
                        uint32_t abase = sb + TC_STAGE0 + (uint32_t)buf * STAGE_BYTES;
                        unsigned long long ad = make_desc(abase);
                        unsigned long long bd = make_desc(abase + 16384u);
                        uint32_t dcol = tmem_base + (uint32_t)((tc & 1) * 256);
#pragma unroll
                        for (int p = 0; p < 3; p++) {
                            const int ao = (p == 2) ? 4 : 0;
                            const int bo = (p == 1) ? 4 : 0;
#pragma unroll
                            for (int ks = 0; ks < 2; ks++) {
                                uint32_t en = (s == 0 && p == 0 && ks == 0) ? 0u : 1u;
                                mma_f16_ss_cg2(dcol, ad + ao + ks * 2, bd + bo + ks * 2, en);
                            }
                        }
                        TCGEN05_COMMIT_MC(sb + MB_MMA + buf * 8);
                        if (s == 7) TCGEN05_COMMIT_MC(sb + MB_DONE + (tc & 1) * 8);
                    } else {
                        MBARRIER_ARRIVE_LEADER(sb + MB_RDY + buf * 8);
                    }

                    // buffer (lc+STAGES-1)%STAGES was last used by chunk lc-1
                    if (lc >= 1)
                        MBARRIER_WAIT_PARITY(sb + MB_MMA + ((lc - 1) % STAGES) * 8,
                                             (uint32_t)(((lc - 1) / STAGES) & 1));
                    issue_load(lc + STAGES - 1);
                }
            }
        }
    } else {
        // ================== EPILOGUE (warps 0-7, each CTA reads its own D) ==================
        const int w = tid >> 5;
        const int lane = tid & 31;
        const int sub = w & 3;
        const int grp = w >> 2;   // col half within N=256
        float* en = (float*)(smem + TC_EN_OFF);
        int tc = 0;
        for (int t = cid; t < N_TILES; t += N_CLUSTERS, tc++) {
            const int nt = t & 31;
            const int mt = t >> 5;
            en[tid] = g_enorm[nt * 256 + tid];
            asm volatile("bar.sync 1, 256;" ::: "memory");

            MBARRIER_WAIT_PARITY(sb + MB_DONE + (tc & 1) * 8, (uint32_t)((tc >> 1) & 1));
            TCGEN05_FENCE_AFTER();

            const uint32_t dbase = tmem_base + (uint32_t)((tc & 1) * 256) + grp * 128;
            float dmin = 3.4e38f;
            int besti = 0;
#pragma unroll
            for (int c0 = 0; c0 < 128; c0 += 32) {
                uint32_t r[32];
                TCGEN05_LD_32X32B_X32(r, dbase + c0);
                TCGEN05_WAIT_LD();
#pragma unroll
                for (int j = 0; j < 32; j++) {
                    int nl = grp * 128 + c0 + j;
                    float d = en[nl] - 2.0f * __uint_as_float(r[j]);
                    if (d < dmin) { dmin = d; besti = nl; }
                }
            }
            TCGEN05_FENCE_BEFORE();
            asm volatile("bar.sync 1, 256;" ::: "memory");  // all D + en reads done
            if (tid == 0) {
                if (rank == 0) MBARRIER_ARRIVE(sb + MB_EPI + (tc & 1) * 8);
                else MBARRIER_ARRIVE_LEADER(sb + MB_EPI + (tc & 1) * 8);
            }

            const int mrow = mt * 256 + (int)rank * 128 + sub * 32 + lane;
            unsigned long long key =
                ((unsigned long long)fkey(dmin) << 32) | (unsigned)(nt * 256 + besti);
            atomicMin(&g_best[mrow], key);
        }
    }

    __syncthreads();
    if ((tid >> 5) == 8) TCGEN05_DEALLOC_CG2(tmem_base, 512);
    CLUSTER_SYNC();

#else
    // PTX-pass body: compile-only; the sm_103a cubin above is what executes.
    (void)tid;
#endif
}

// ---------------- gather + loss ----------------
// loss per row recovered from the argmin key: ||q-z||^2 = dmin + ||z||^2
// 512 threads: 8 rows per block, one float4 per thread.
__global__ void gather_kernel(const float* __restrict__ emb,
                              float* __restrict__ out, int has_extra) {
    const int tid = threadIdx.x;
    const int r = tid >> 6;
    const int c = tid & 63;
    const int row = blockIdx.x * 8 + r;
    unsigned long long key = g_best[row];
    int idx = (int)(key & 0xFFFFFFFFull);

    ((float4*)out)[(size_t)row * 64 + c] = ((const float4*)emb)[(size_t)idx * 64 + c];

    if (c == 0) {
        g_partial[row] = unfkey((unsigned)(key >> 32)) + g_znorm[row];
        if (has_extra) out[Q_ELEMS + 1 + row] = (float)idx;
    }
}

// 1024 threads, float4 loads: 16384 floats = 4 coalesced iterations/thread.
__global__ void finalize_kernel(float* __restrict__ out, int has_extra) {
    if (!has_extra) return;
    __shared__ float sh[1024];
    const int tid = threadIdx.x;
    float s = 0.f;
    const float4* p4 = (const float4*)g_partial;
#pragma unroll
    for (int i = 0; i < 4; i++) {
        float4 v = p4[tid + i * 1024];
        s += (v.x + v.y) + (v.z + v.w);
    }
    sh[tid] = s;
    __syncthreads();
#pragma unroll
    for (int o = 512; o >= 32; o >>= 1) {
        if (tid < o) sh[tid] += sh[tid + o];
        __syncthreads();
    }
    if (tid < 32) {
        float v = sh[tid];
#pragma unroll
        for (int o = 16; o; o >>= 1) v += __shfl_xor_sync(0xffffffffu, v, o);
        if (tid == 0) out[Q_ELEMS] = 1.25f * v / (float)Q_ELEMS;
    }
}

// ---------------- launcher ----------------
extern "C" void kernel_launch(void* const* d_in, const int* in_sizes, int n_in,
                              void* d_out, int out_size) {
    const float* z;
    const float* emb;
    if (in_sizes[0] == M_ROWS * KDIM) {
        z = (const float*)d_in[0];
        emb = (const float*)d_in[1];
    } else {
        z = (const float*)d_in[1];
        emb = (const float*)d_in[0];
    }
    float* out = (float*)d_out;
    int has_extra = (out_size >= Q_ELEMS + 1 + M_ROWS) ? 1 : 0;

    cudaFuncSetAttribute(vq_gemm_kernel,
                         cudaFuncAttributeMaxDynamicSharedMemorySize, TC_TOTAL);

    pack_kernel<<<3072, 256>>>(z, emb);   // z blocks [0,2048), e blocks [2048,3072)

    vq_gemm_kernel<<<2 * N_CLUSTERS, THREADS, TC_TOTAL>>>();

    gather_kernel<<<M_ROWS / 8, 512>>>(emb, out, has_extra);
    finalize_kernel<<<1, 1024>>>(out, has_extra);
}